// round 10
// baseline (speedup 1.0000x reference)
#include <cuda_runtime.h>
#include <cuda_bf16.h>
#include <mma.h>
#include <cstdint>

using namespace nvcuda;

#define N_NODES 50000
#define N_EDGES 800000
#define DIM 128
#define NLAYERS 3
#define CAP 64                       // adjacency capacity per node (deg: mean 16, sigma 4)
#define NBLK_NODE 196                // ceil(50000/256)
#define GEMM_BLOCKS 391              // ceil(50000/128)
#define EDGE_BLOCKS 3125             // ceil(800000/256)

// ---------------------------------------------------------------------------
// Scratch (no allocations allowed -> __device__ globals)
// ---------------------------------------------------------------------------
__device__ float g_h[N_NODES * DIM];
__device__ float g_agg[N_NODES * DIM];
__device__ int   g_cnt[N_NODES];
__device__ int   g_adj[N_NODES * CAP];

// ---------------------------------------------------------------------------
// bf16 hi/lo split of a pair of floats, packed as bf16x2 words
// ---------------------------------------------------------------------------
__device__ __forceinline__ void split2(float a0, float a1, uint32_t& hi, uint32_t& lo) {
    __nv_bfloat16 h0 = __float2bfloat16(a0);
    __nv_bfloat16 h1 = __float2bfloat16(a1);
    float r0 = a0 - __bfloat162float(h0);
    float r1 = a1 - __bfloat162float(h1);
    __nv_bfloat16 l0 = __float2bfloat16(r0);
    __nv_bfloat16 l1 = __float2bfloat16(r1);
    hi = (uint32_t)__bfloat16_as_ushort(h0) | ((uint32_t)__bfloat16_as_ushort(h1) << 16);
    lo = (uint32_t)__bfloat16_as_ushort(l0) | ((uint32_t)__bfloat16_as_ushort(l1) << 16);
}

// Staging buffer offsets (bytes)
#define A_HI 0
#define A_LO 10240
#define W_HI 20480
#define W_LO 29184
#define SMEM_BYTES 37888   // also reused as 8 warps x 16x68 fp32 epilogue scratch

// ---------------------------------------------------------------------------
// GEMM body: 128x128 CTA tile, bf16x3 split, 8 warps as 4(m) x 2(n).
//   FUSED=false: out = A1 @ W1 + bias                       (K=128)
//   FUSED=true : out = relu([A1|A2] @ [W1;W2] + bias) + A2  (K=256)
// ---------------------------------------------------------------------------
template <bool FUSED>
__device__ __forceinline__ void gemm_body(
    const float* __restrict__ A1, const float* __restrict__ W1,
    const float* __restrict__ A2, const float* __restrict__ W2,
    const float* __restrict__ bias, float* __restrict__ out,
    int row0, char* smem_raw)
{
    const int tid  = threadIdx.x;
    const int wid  = tid >> 5;
    const int lane = tid & 31;
    const int wm   = wid & 3;
    const int wn   = wid >> 2;

    constexpr int NCHUNK = FUSED ? 8 : 4;

    wmma::fragment<wmma::accumulator, 16, 16, 16, float> acc[2][4];
#pragma unroll
    for (int mi = 0; mi < 2; mi++)
#pragma unroll
        for (int ni = 0; ni < 4; ni++)
            wmma::fill_fragment(acc[mi][ni], 0.0f);

    for (int kc = 0; kc < NCHUNK; kc++) {
        const int k0 = kc * 32;
        __syncthreads();

        // --- stage A chunk ---
#pragma unroll
        for (int t = 0; t < 4; t++) {
            int q  = tid + t * 256;
            int r  = q >> 3;
            int c4 = q & 7;
            int col = k0 + c4 * 4;
            int gr  = row0 + r;
            float4 v = make_float4(0.f, 0.f, 0.f, 0.f);
            if (gr < N_NODES) {
                const float* base = (!FUSED || col < 128) ? A1 : A2;
                int cc = (!FUSED || col < 128) ? col : col - 128;
                v = *reinterpret_cast<const float4*>(base + (size_t)gr * DIM + cc);
            }
            uint32_t h0, l0, h1, l1;
            split2(v.x, v.y, h0, l0);
            split2(v.z, v.w, h1, l1);
            uint32_t boff = (uint32_t)r * 80u + (uint32_t)c4 * 8u;
            *reinterpret_cast<uint2*>(smem_raw + A_HI + boff) = make_uint2(h0, h1);
            *reinterpret_cast<uint2*>(smem_raw + A_LO + boff) = make_uint2(l0, l1);
        }

        // --- stage W chunk ---
#pragma unroll
        for (int t = 0; t < 4; t++) {
            int q  = tid + t * 256;
            int kk = q >> 5;
            int c4 = q & 31;
            int krow = k0 + kk;
            const float* base = (!FUSED || krow < 128) ? W1 : W2;
            int kr = (!FUSED || krow < 128) ? krow : krow - 128;
            float4 v = *reinterpret_cast<const float4*>(base + (size_t)kr * DIM + c4 * 4);
            uint32_t h0, l0, h1, l1;
            split2(v.x, v.y, h0, l0);
            split2(v.z, v.w, h1, l1);
            uint32_t boff = (uint32_t)kk * 272u + (uint32_t)c4 * 8u;
            *reinterpret_cast<uint2*>(smem_raw + W_HI + boff) = make_uint2(h0, h1);
            *reinterpret_cast<uint2*>(smem_raw + W_LO + boff) = make_uint2(l0, l1);
        }
        __syncthreads();

        // --- MMA: 2 k-steps of 16 ---
#pragma unroll
        for (int ks = 0; ks < 2; ks++) {
            wmma::fragment<wmma::matrix_a, 16, 16, 16, __nv_bfloat16, wmma::row_major> ah[2], al[2];
#pragma unroll
            for (int mi = 0; mi < 2; mi++) {
                const __nv_bfloat16* pa_hi = reinterpret_cast<const __nv_bfloat16*>(smem_raw + A_HI)
                                           + (wm * 32 + mi * 16) * 40 + ks * 16;
                const __nv_bfloat16* pa_lo = reinterpret_cast<const __nv_bfloat16*>(smem_raw + A_LO)
                                           + (wm * 32 + mi * 16) * 40 + ks * 16;
                wmma::load_matrix_sync(ah[mi], pa_hi, 40);
                wmma::load_matrix_sync(al[mi], pa_lo, 40);
            }
#pragma unroll
            for (int ni = 0; ni < 4; ni++) {
                wmma::fragment<wmma::matrix_b, 16, 16, 16, __nv_bfloat16, wmma::row_major> bh, bl;
                const __nv_bfloat16* pb_hi = reinterpret_cast<const __nv_bfloat16*>(smem_raw + W_HI)
                                           + (ks * 16) * 136 + wn * 64 + ni * 16;
                const __nv_bfloat16* pb_lo = reinterpret_cast<const __nv_bfloat16*>(smem_raw + W_LO)
                                           + (ks * 16) * 136 + wn * 64 + ni * 16;
                wmma::load_matrix_sync(bh, pb_hi, 136);
                wmma::load_matrix_sync(bl, pb_lo, 136);
#pragma unroll
                for (int mi = 0; mi < 2; mi++) {
                    wmma::mma_sync(acc[mi][ni], ah[mi], bh, acc[mi][ni]);
                    wmma::mma_sync(acc[mi][ni], ah[mi], bl, acc[mi][ni]);
                    wmma::mma_sync(acc[mi][ni], al[mi], bh, acc[mi][ni]);
                }
            }
        }
    }

    // --- epilogue ---
    __syncthreads();
    float* sc = reinterpret_cast<float*>(smem_raw) + wid * (16 * 68);
    const int col0 = wn * 64;
    const int rl   = lane >> 1;
    const int half = lane & 1;

#pragma unroll
    for (int mi = 0; mi < 2; mi++) {
#pragma unroll
        for (int ni = 0; ni < 4; ni++)
            wmma::store_matrix_sync(sc + ni * 16, acc[mi][ni], 68, wmma::mem_row_major);
        __syncwarp();

        int grow = row0 + wm * 32 + mi * 16 + rl;
        if (grow < N_NODES) {
#pragma unroll
            for (int j = 0; j < 8; j++) {
                int c = half * 32 + j * 4;
                float4 v = *reinterpret_cast<const float4*>(sc + rl * 68 + c);
                float4 b4 = *reinterpret_cast<const float4*>(bias + col0 + c);
                v.x += b4.x; v.y += b4.y; v.z += b4.z; v.w += b4.w;
                if (FUSED) {
                    v.x = fmaxf(v.x, 0.f); v.y = fmaxf(v.y, 0.f);
                    v.z = fmaxf(v.z, 0.f); v.w = fmaxf(v.w, 0.f);
                    float4 rr = *reinterpret_cast<const float4*>(A2 + (size_t)grow * DIM + col0 + c);
                    v.x += rr.x; v.y += rr.y; v.z += rr.z; v.w += rr.w;
                }
                *reinterpret_cast<float4*>(out + (size_t)grow * DIM + col0 + c) = v;
            }
        }
        __syncwarp();
    }
}

// ---------------------------------------------------------------------------
// Kernels
// ---------------------------------------------------------------------------
__global__ void zero_cnt_kernel() {
    int i = blockIdx.x * blockDim.x + threadIdx.x;
    if (i < N_NODES) g_cnt[i] = 0;
}

// Heterogeneous: blocks [0,GEMM_BLOCKS) -> in_fc GEMM; rest -> adjacency fill.
// Both independent; next kernel (aggregate) needs both -> overlap is free.
__global__ __launch_bounds__(256) void infc_fill_kernel(
    const float* __restrict__ x, const float* __restrict__ W,
    const float* __restrict__ bias, const int* __restrict__ src,
    const int* __restrict__ dst, float* __restrict__ h)
{
    __shared__ __align__(16) char smem_raw[SMEM_BYTES];
    if (blockIdx.x < GEMM_BLOCKS) {
        gemm_body<false>(x, W, nullptr, nullptr, bias, h, blockIdx.x * 128, smem_raw);
    } else {
        int e = (blockIdx.x - GEMM_BLOCKS) * 256 + threadIdx.x;
        if (e < N_EDGES) {
            int d = dst[e];
            int pos = atomicAdd(&g_cnt[d], 1);
            if (pos < CAP) g_adj[(size_t)d * CAP + pos] = src[e];
        }
    }
}

__global__ __launch_bounds__(256) void layer_gemm_kernel(
    const float* __restrict__ Wrel, const float* __restrict__ Wroot,
    const float* __restrict__ h, const float* __restrict__ bias,
    float* __restrict__ out)
{
    __shared__ __align__(16) char smem_raw[SMEM_BYTES];
    gemm_body<true>(g_agg, Wrel, h, Wroot, bias, out, blockIdx.x * 128, smem_raw);
}

// Aggregate: one warp per node; serial index walk (TLP hides latency).
__global__ __launch_bounds__(256) void aggregate_kernel() {
    const int node = (blockIdx.x * blockDim.x + threadIdx.x) >> 5;
    const int lane = threadIdx.x & 31;
    if (node >= N_NODES) return;
    int cnt = g_cnt[node];
    if (cnt > CAP) cnt = CAP;
    const int* __restrict__ lst = g_adj + (size_t)node * CAP;
    const float4* __restrict__ h4 = reinterpret_cast<const float4*>(g_h);
    float4 acc = make_float4(0.f, 0.f, 0.f, 0.f);
    for (int i = 0; i < cnt; i++) {
        int s = lst[i];
        float4 v = h4[(size_t)s * 32 + lane];
        acc.x += v.x; acc.y += v.y; acc.z += v.z; acc.w += v.w;
    }
    reinterpret_cast<float4*>(g_agg)[(size_t)node * 32 + lane] = acc;
}

// ---------------------------------------------------------------------------
// Launch (single stream)
// ---------------------------------------------------------------------------
extern "C" void kernel_launch(void* const* d_in, const int* in_sizes, int n_in,
                              void* d_out, int out_size)
{
    const float* x       = (const float*)d_in[0];
    const int*   ei      = (const int*)  d_in[1];
    const float* in_fc_w = (const float*)d_in[2];
    const float* in_fc_b = (const float*)d_in[3];
    const float* w_rel   = (const float*)d_in[4];
    const float* b_rel   = (const float*)d_in[5];
    const float* w_root  = (const float*)d_in[6];
    float* out = (float*)d_out;

    const int* src = ei;
    const int* dst = ei + N_EDGES;

    float* h_ptr; cudaGetSymbolAddress((void**)&h_ptr, g_h);

    const int AGG_BLOCKS = (N_NODES * 32 + 255) / 256;   // 1 warp per node

    // Adjacency build (2 kernels) with fill overlapped against in_fc GEMM
    zero_cnt_kernel<<<NBLK_NODE, 256>>>();
    infc_fill_kernel<<<GEMM_BLOCKS + EDGE_BLOCKS, 256>>>(
        x, in_fc_w, in_fc_b, src, dst, h_ptr);

    // 3 GraphConv layers: out = relu(agg@w_rel + h@w_root + b) + h
    for (int l = 0; l < NLAYERS; l++) {
        aggregate_kernel<<<AGG_BLOCKS, 256>>>();
        float* dst_buf = (l == NLAYERS - 1) ? out : h_ptr;
        layer_gemm_kernel<<<GEMM_BLOCKS, 256>>>(
            w_rel + (size_t)l * DIM * DIM, w_root + (size_t)l * DIM * DIM,
            h_ptr, b_rel + (size_t)l * DIM, dst_buf);
    }
}

// round 11
// speedup vs baseline: 1.1772x; 1.1772x over previous
#include <cuda_runtime.h>
#include <cuda_bf16.h>
#include <cuda_pipeline.h>
#include <mma.h>
#include <cstdint>

using namespace nvcuda;

#define N_NODES 50000
#define N_EDGES 800000
#define DIM 128
#define NLAYERS 3
#define CAP 64
#define NBLK_NODE 196                // ceil(50000/256)
#define GEMM_BLOCKS 391              // ceil(50000/128)
#define EDGE_BLOCKS 3125             // ceil(800000/256)

// ---------------------------------------------------------------------------
// Scratch (__device__ globals; no allocations allowed)
// ---------------------------------------------------------------------------
__device__ float    g_h[N_NODES * DIM];              // fp32 h (residual + gather)
__device__ uint32_t g_h_hi[N_NODES * 64];            // h as bf16x2 hi
__device__ uint32_t g_h_lo[N_NODES * 64];            // h as bf16x2 lo
__device__ uint32_t g_agg_hi[N_NODES * 64];          // agg as bf16x2 hi
__device__ uint32_t g_agg_lo[N_NODES * 64];          // agg as bf16x2 lo
__device__ uint32_t g_w_hi[NLAYERS * 256 * 64];      // [w_rel;w_root] bf16x2 hi
__device__ uint32_t g_w_lo[NLAYERS * 256 * 64];      // [w_rel;w_root] bf16x2 lo
__device__ int      g_cnt[N_NODES];
__device__ int      g_adj[N_NODES * CAP];

// ---------------------------------------------------------------------------
// bf16 hi/lo split of a pair of floats, packed as bf16x2 words
// ---------------------------------------------------------------------------
__device__ __forceinline__ void split2(float a0, float a1, uint32_t& hi, uint32_t& lo) {
    __nv_bfloat16 h0 = __float2bfloat16(a0);
    __nv_bfloat16 h1 = __float2bfloat16(a1);
    float r0 = a0 - __bfloat162float(h0);
    float r1 = a1 - __bfloat162float(h1);
    __nv_bfloat16 l0 = __float2bfloat16(r0);
    __nv_bfloat16 l1 = __float2bfloat16(r1);
    hi = (uint32_t)__bfloat16_as_ushort(h0) | ((uint32_t)__bfloat16_as_ushort(h1) << 16);
    lo = (uint32_t)__bfloat16_as_ushort(l0) | ((uint32_t)__bfloat16_as_ushort(l1) << 16);
}

// Staging layout within one pipeline buffer (bytes)
#define A_HI 0            // 128 x 32 bf16, ldm 40  -> 10240 B
#define A_LO 10240
#define W_HI 20480        // 32 x 128 bf16, ldm 136 -> 8704 B
#define W_LO 29184
#define BUF_BYTES 37888
#define DSM_BYTES (2 * BUF_BYTES)    // 75776; 2 CTAs/SM -> 148 KB < 228 KB

// ===========================================================================
// Pre-split weights: g_w_{hi,lo}[l] rows 0-127 = w_rel[l], 128-255 = w_root[l]
// ===========================================================================
__global__ void split_w_kernel(const float* __restrict__ w_rel,
                               const float* __restrict__ w_root) {
    int w = blockIdx.x * blockDim.x + threadIdx.x;      // word index
    if (w >= NLAYERS * 256 * 64) return;
    int l  = w / (256 * 64);
    int r  = (w >> 6) & 255;
    int c2 = w & 63;
    const float* srcm = (r < 128) ? (w_rel + (size_t)l * DIM * DIM + r * DIM)
                                  : (w_root + (size_t)l * DIM * DIM + (r - 128) * DIM);
    float a0 = srcm[c2 * 2];
    float a1 = srcm[c2 * 2 + 1];
    uint32_t hi, lo;
    split2(a0, a1, hi, lo);
    g_w_hi[w] = hi;
    g_w_lo[w] = lo;
}

// ===========================================================================
// in_fc GEMM (K=128, fp32 inputs, split in-kernel — runs once) + edge fill
// ===========================================================================
__global__ __launch_bounds__(256) void infc_fill_kernel(
    const float* __restrict__ x, const float* __restrict__ W,
    const float* __restrict__ bias, const int* __restrict__ src,
    const int* __restrict__ dst, float* __restrict__ h)
{
    __shared__ __align__(16) char smem_raw[BUF_BYTES];

    if (blockIdx.x >= GEMM_BLOCKS) {
        int e = (blockIdx.x - GEMM_BLOCKS) * 256 + threadIdx.x;
        if (e < N_EDGES) {
            int d = dst[e];
            int pos = atomicAdd(&g_cnt[d], 1);
            if (pos < CAP) g_adj[(size_t)d * CAP + pos] = src[e];
        }
        return;
    }

    const int tid  = threadIdx.x;
    const int wid  = tid >> 5;
    const int lane = tid & 31;
    const int wm   = wid & 3;
    const int wn   = wid >> 2;
    const int row0 = blockIdx.x * 128;

    wmma::fragment<wmma::accumulator, 16, 16, 16, float> acc[2][4];
#pragma unroll
    for (int mi = 0; mi < 2; mi++)
#pragma unroll
        for (int ni = 0; ni < 4; ni++)
            wmma::fill_fragment(acc[mi][ni], 0.0f);

    for (int kc = 0; kc < 4; kc++) {
        const int k0 = kc * 32;
        __syncthreads();
#pragma unroll
        for (int t = 0; t < 4; t++) {
            int q  = tid + t * 256;
            int r  = q >> 3;
            int c4 = q & 7;
            int gr = row0 + r;
            float4 v = make_float4(0.f, 0.f, 0.f, 0.f);
            if (gr < N_NODES)
                v = *reinterpret_cast<const float4*>(x + (size_t)gr * DIM + k0 + c4 * 4);
            uint32_t h0, l0, h1, l1;
            split2(v.x, v.y, h0, l0);
            split2(v.z, v.w, h1, l1);
            uint32_t boff = (uint32_t)r * 80u + (uint32_t)c4 * 8u;
            *reinterpret_cast<uint2*>(smem_raw + A_HI + boff) = make_uint2(h0, h1);
            *reinterpret_cast<uint2*>(smem_raw + A_LO + boff) = make_uint2(l0, l1);
        }
#pragma unroll
        for (int t = 0; t < 4; t++) {
            int q  = tid + t * 256;
            int kk = q >> 5;
            int c4 = q & 31;
            float4 v = *reinterpret_cast<const float4*>(W + (size_t)(k0 + kk) * DIM + c4 * 4);
            uint32_t h0, l0, h1, l1;
            split2(v.x, v.y, h0, l0);
            split2(v.z, v.w, h1, l1);
            uint32_t boff = (uint32_t)kk * 272u + (uint32_t)c4 * 8u;
            *reinterpret_cast<uint2*>(smem_raw + W_HI + boff) = make_uint2(h0, h1);
            *reinterpret_cast<uint2*>(smem_raw + W_LO + boff) = make_uint2(l0, l1);
        }
        __syncthreads();

#pragma unroll
        for (int ks = 0; ks < 2; ks++) {
            wmma::fragment<wmma::matrix_a, 16, 16, 16, __nv_bfloat16, wmma::row_major> ah[2], al[2];
#pragma unroll
            for (int mi = 0; mi < 2; mi++) {
                const __nv_bfloat16* pa_hi = reinterpret_cast<const __nv_bfloat16*>(smem_raw + A_HI)
                                           + (wm * 32 + mi * 16) * 40 + ks * 16;
                const __nv_bfloat16* pa_lo = reinterpret_cast<const __nv_bfloat16*>(smem_raw + A_LO)
                                           + (wm * 32 + mi * 16) * 40 + ks * 16;
                wmma::load_matrix_sync(ah[mi], pa_hi, 40);
                wmma::load_matrix_sync(al[mi], pa_lo, 40);
            }
#pragma unroll
            for (int ni = 0; ni < 4; ni++) {
                wmma::fragment<wmma::matrix_b, 16, 16, 16, __nv_bfloat16, wmma::row_major> bh, bl;
                const __nv_bfloat16* pb_hi = reinterpret_cast<const __nv_bfloat16*>(smem_raw + W_HI)
                                           + (ks * 16) * 136 + wn * 64 + ni * 16;
                const __nv_bfloat16* pb_lo = reinterpret_cast<const __nv_bfloat16*>(smem_raw + W_LO)
                                           + (ks * 16) * 136 + wn * 64 + ni * 16;
                wmma::load_matrix_sync(bh, pb_hi, 136);
                wmma::load_matrix_sync(bl, pb_lo, 136);
#pragma unroll
                for (int mi = 0; mi < 2; mi++) {
                    wmma::mma_sync(acc[mi][ni], ah[mi], bh, acc[mi][ni]);
                    wmma::mma_sync(acc[mi][ni], ah[mi], bl, acc[mi][ni]);
                    wmma::mma_sync(acc[mi][ni], al[mi], bh, acc[mi][ni]);
                }
            }
        }
    }

    __syncthreads();
    float* sc = reinterpret_cast<float*>(smem_raw) + wid * (16 * 68);
    const int col0 = wn * 64;
    const int rl   = lane >> 1;
    const int half = lane & 1;
#pragma unroll
    for (int mi = 0; mi < 2; mi++) {
#pragma unroll
        for (int ni = 0; ni < 4; ni++)
            wmma::store_matrix_sync(sc + ni * 16, acc[mi][ni], 68, wmma::mem_row_major);
        __syncwarp();
        int grow = row0 + wm * 32 + mi * 16 + rl;
        if (grow < N_NODES) {
#pragma unroll
            for (int j = 0; j < 8; j++) {
                int c = half * 32 + j * 4;
                float4 v  = *reinterpret_cast<const float4*>(sc + rl * 68 + c);
                float4 b4 = *reinterpret_cast<const float4*>(bias + col0 + c);
                v.x += b4.x; v.y += b4.y; v.z += b4.z; v.w += b4.w;
                *reinterpret_cast<float4*>(h + (size_t)grow * DIM + col0 + c) = v;
                uint32_t h0, l0, h1, l1;
                split2(v.x, v.y, h0, l0);
                split2(v.z, v.w, h1, l1);
                size_t wi = (size_t)grow * 64 + (col0 + c) / 2;
                *reinterpret_cast<uint2*>(&g_h_hi[wi]) = make_uint2(h0, h1);
                *reinterpret_cast<uint2*>(&g_h_lo[wi]) = make_uint2(l0, l1);
            }
        }
        __syncwarp();
    }
}

// ===========================================================================
// Layer GEMM: out = relu([agg|h] @ Wcat + bias) + h
// Pre-split bf16 operands, cp.async double-buffered pipeline, 2 CTAs/SM.
// ===========================================================================
template <bool WRITE_BF16>
__global__ __launch_bounds__(256, 2) void layer_gemm_kernel(
    const uint32_t* __restrict__ w_hi, const uint32_t* __restrict__ w_lo,
    const float* __restrict__ h, const float* __restrict__ bias,
    float* __restrict__ out)
{
    extern __shared__ __align__(16) char dsm[];

    const int tid  = threadIdx.x;
    const int wid  = tid >> 5;
    const int lane = tid & 31;
    const int wm   = wid & 3;
    const int wn   = wid >> 2;
    const int row0 = blockIdx.x * 128;

    wmma::fragment<wmma::accumulator, 16, 16, 16, float> acc[2][4];
#pragma unroll
    for (int mi = 0; mi < 2; mi++)
#pragma unroll
        for (int ni = 0; ni < 4; ni++)
            wmma::fill_fragment(acc[mi][ni], 0.0f);

    const uint4* w_hi4 = reinterpret_cast<const uint4*>(w_hi);
    const uint4* w_lo4 = reinterpret_cast<const uint4*>(w_lo);

    // Stage chunk kc into buffer kc&1 (8 x 16B cp.async per thread)
    auto stage = [&](int kc) {
        char* buf = dsm + (kc & 1) * BUF_BYTES;
        const int k0 = kc * 32;
        const uint4* sa_hi;
        const uint4* sa_lo;
        int colb;
        if (k0 < 128) {
            sa_hi = reinterpret_cast<const uint4*>(g_agg_hi);
            sa_lo = reinterpret_cast<const uint4*>(g_agg_lo);
            colb  = k0 >> 3;
        } else {
            sa_hi = reinterpret_cast<const uint4*>(g_h_hi);
            sa_lo = reinterpret_cast<const uint4*>(g_h_lo);
            colb  = (k0 - 128) >> 3;
        }
#pragma unroll
        for (int t = 0; t < 2; t++) {
            int q  = tid + t * 256;          // 0..511
            int r  = q >> 2;
            int c8 = q & 3;
            int rg = min(row0 + r, N_NODES - 1);
            __pipeline_memcpy_async(buf + A_HI + r * 80 + c8 * 16,
                                    sa_hi + (size_t)rg * 16 + colb + c8, 16);
            __pipeline_memcpy_async(buf + A_LO + r * 80 + c8 * 16,
                                    sa_lo + (size_t)rg * 16 + colb + c8, 16);
        }
#pragma unroll
        for (int t = 0; t < 2; t++) {
            int q  = tid + t * 256;          // 0..511
            int kk = q >> 4;
            int c8 = q & 15;
            __pipeline_memcpy_async(buf + W_HI + kk * 272 + c8 * 16,
                                    w_hi4 + (size_t)(k0 + kk) * 16 + c8, 16);
            __pipeline_memcpy_async(buf + W_LO + kk * 272 + c8 * 16,
                                    w_lo4 + (size_t)(k0 + kk) * 16 + c8, 16);
        }
        __pipeline_commit();
    };

    stage(0);
    for (int kc = 0; kc < 8; kc++) {
        if (kc < 7) stage(kc + 1);
        __pipeline_wait_prior(kc < 7 ? 1 : 0);
        __syncthreads();

        const char* buf = dsm + (kc & 1) * BUF_BYTES;
#pragma unroll
        for (int ks = 0; ks < 2; ks++) {
            wmma::fragment<wmma::matrix_a, 16, 16, 16, __nv_bfloat16, wmma::row_major> ah[2], al[2];
#pragma unroll
            for (int mi = 0; mi < 2; mi++) {
                const __nv_bfloat16* pa_hi = reinterpret_cast<const __nv_bfloat16*>(buf + A_HI)
                                           + (wm * 32 + mi * 16) * 40 + ks * 16;
                const __nv_bfloat16* pa_lo = reinterpret_cast<const __nv_bfloat16*>(buf + A_LO)
                                           + (wm * 32 + mi * 16) * 40 + ks * 16;
                wmma::load_matrix_sync(ah[mi], pa_hi, 40);
                wmma::load_matrix_sync(al[mi], pa_lo, 40);
            }
#pragma unroll
            for (int ni = 0; ni < 4; ni++) {
                wmma::fragment<wmma::matrix_b, 16, 16, 16, __nv_bfloat16, wmma::row_major> bh, bl;
                const __nv_bfloat16* pb_hi = reinterpret_cast<const __nv_bfloat16*>(buf + W_HI)
                                           + (ks * 16) * 136 + wn * 64 + ni * 16;
                const __nv_bfloat16* pb_lo = reinterpret_cast<const __nv_bfloat16*>(buf + W_LO)
                                           + (ks * 16) * 136 + wn * 64 + ni * 16;
                wmma::load_matrix_sync(bh, pb_hi, 136);
                wmma::load_matrix_sync(bl, pb_lo, 136);
#pragma unroll
                for (int mi = 0; mi < 2; mi++) {
                    wmma::mma_sync(acc[mi][ni], ah[mi], bh, acc[mi][ni]);
                    wmma::mma_sync(acc[mi][ni], ah[mi], bl, acc[mi][ni]);
                    wmma::mma_sync(acc[mi][ni], al[mi], bh, acc[mi][ni]);
                }
            }
        }
        __syncthreads();
    }

    // Epilogue: bias + relu + residual (+ optional bf16 hi/lo h write)
    float* sc = reinterpret_cast<float*>(dsm) + wid * (16 * 68);
    const int col0 = wn * 64;
    const int rl   = lane >> 1;
    const int half = lane & 1;
#pragma unroll
    for (int mi = 0; mi < 2; mi++) {
#pragma unroll
        for (int ni = 0; ni < 4; ni++)
            wmma::store_matrix_sync(sc + ni * 16, acc[mi][ni], 68, wmma::mem_row_major);
        __syncwarp();
        int grow = row0 + wm * 32 + mi * 16 + rl;
        if (grow < N_NODES) {
#pragma unroll
            for (int j = 0; j < 8; j++) {
                int c = half * 32 + j * 4;
                float4 v  = *reinterpret_cast<const float4*>(sc + rl * 68 + c);
                float4 b4 = *reinterpret_cast<const float4*>(bias + col0 + c);
                v.x += b4.x; v.y += b4.y; v.z += b4.z; v.w += b4.w;
                v.x = fmaxf(v.x, 0.f); v.y = fmaxf(v.y, 0.f);
                v.z = fmaxf(v.z, 0.f); v.w = fmaxf(v.w, 0.f);
                float4 rr = *reinterpret_cast<const float4*>(h + (size_t)grow * DIM + col0 + c);
                v.x += rr.x; v.y += rr.y; v.z += rr.z; v.w += rr.w;
                *reinterpret_cast<float4*>(out + (size_t)grow * DIM + col0 + c) = v;
                if (WRITE_BF16) {
                    uint32_t h0, l0, h1, l1;
                    split2(v.x, v.y, h0, l0);
                    split2(v.z, v.w, h1, l1);
                    size_t wi = (size_t)grow * 64 + (col0 + c) / 2;
                    *reinterpret_cast<uint2*>(&g_h_hi[wi]) = make_uint2(h0, h1);
                    *reinterpret_cast<uint2*>(&g_h_lo[wi]) = make_uint2(l0, l1);
                }
            }
        }
        __syncwarp();
    }
}

// ===========================================================================
// Misc small kernels
// ===========================================================================
__global__ void zero_cnt_kernel() {
    int i = blockIdx.x * blockDim.x + threadIdx.x;
    if (i < N_NODES) g_cnt[i] = 0;
}

// Aggregate: one warp per node; coalesced index load + shfl broadcast, MLP=4.
// Writes agg directly as bf16 hi/lo.
__global__ __launch_bounds__(256) void aggregate_kernel() {
    const int node = (blockIdx.x * blockDim.x + threadIdx.x) >> 5;
    const int lane = threadIdx.x & 31;
    if (node >= N_NODES) return;
    int cnt = g_cnt[node];
    if (cnt > CAP) cnt = CAP;
    const int* __restrict__ lst = g_adj + (size_t)node * CAP;
    const float4* __restrict__ h4 = reinterpret_cast<const float4*>(g_h);
    float4 acc = make_float4(0.f, 0.f, 0.f, 0.f);
    for (int base = 0; base < cnt; base += 32) {
        int c = min(cnt - base, 32);
        int idx = (lane < c) ? lst[base + lane] : 0;
        int j = 0;
        for (; j + 4 <= c; j += 4) {
            int s0 = __shfl_sync(0xFFFFFFFFu, idx, j);
            int s1 = __shfl_sync(0xFFFFFFFFu, idx, j + 1);
            int s2 = __shfl_sync(0xFFFFFFFFu, idx, j + 2);
            int s3 = __shfl_sync(0xFFFFFFFFu, idx, j + 3);
            float4 v0 = h4[(size_t)s0 * 32 + lane];
            float4 v1 = h4[(size_t)s1 * 32 + lane];
            float4 v2 = h4[(size_t)s2 * 32 + lane];
            float4 v3 = h4[(size_t)s3 * 32 + lane];
            acc.x += (v0.x + v1.x) + (v2.x + v3.x);
            acc.y += (v0.y + v1.y) + (v2.y + v3.y);
            acc.z += (v0.z + v1.z) + (v2.z + v3.z);
            acc.w += (v0.w + v1.w) + (v2.w + v3.w);
        }
        for (; j < c; j++) {
            int s0 = __shfl_sync(0xFFFFFFFFu, idx, j);
            float4 v0 = h4[(size_t)s0 * 32 + lane];
            acc.x += v0.x; acc.y += v0.y; acc.z += v0.z; acc.w += v0.w;
        }
    }
    uint32_t h0, l0, h1, l1;
    split2(acc.x, acc.y, h0, l0);
    split2(acc.z, acc.w, h1, l1);
    size_t wi = (size_t)node * 64 + lane * 2;
    *reinterpret_cast<uint2*>(&g_agg_hi[wi]) = make_uint2(h0, h1);
    *reinterpret_cast<uint2*>(&g_agg_lo[wi]) = make_uint2(l0, l1);
}

// ---------------------------------------------------------------------------
// Launch (single stream)
// ---------------------------------------------------------------------------
extern "C" void kernel_launch(void* const* d_in, const int* in_sizes, int n_in,
                              void* d_out, int out_size)
{
    const float* x       = (const float*)d_in[0];
    const int*   ei      = (const int*)  d_in[1];
    const float* in_fc_w = (const float*)d_in[2];
    const float* in_fc_b = (const float*)d_in[3];
    const float* w_rel   = (const float*)d_in[4];
    const float* b_rel   = (const float*)d_in[5];
    const float* w_root  = (const float*)d_in[6];
    float* out = (float*)d_out;

    const int* src = ei;
    const int* dst = ei + N_EDGES;

    float*    h_ptr;  cudaGetSymbolAddress((void**)&h_ptr, g_h);
    uint32_t* whi;    cudaGetSymbolAddress((void**)&whi, g_w_hi);
    uint32_t* wlo;    cudaGetSymbolAddress((void**)&wlo, g_w_lo);

    static int smem_set = 0;
    if (!smem_set) {
        cudaFuncSetAttribute(layer_gemm_kernel<true>,
                             cudaFuncAttributeMaxDynamicSharedMemorySize, DSM_BYTES);
        cudaFuncSetAttribute(layer_gemm_kernel<false>,
                             cudaFuncAttributeMaxDynamicSharedMemorySize, DSM_BYTES);
        smem_set = 1;
    }

    const int AGG_BLOCKS = (N_NODES * 32 + 255) / 256;   // 1 warp per node
    const int WSPLIT_BLOCKS = (NLAYERS * 256 * 64 + 255) / 256;  // 192

    // Adjacency count reset + weight pre-split (independent)
    zero_cnt_kernel<<<NBLK_NODE, 256>>>();
    split_w_kernel<<<WSPLIT_BLOCKS, 256>>>(w_rel, w_root);

    // in_fc GEMM (writes fp32 h + bf16 hi/lo h) overlapped with edge fill
    infc_fill_kernel<<<GEMM_BLOCKS + EDGE_BLOCKS, 256>>>(
        x, in_fc_w, in_fc_b, src, dst, h_ptr);

    // 3 GraphConv layers
    for (int l = 0; l < NLAYERS; l++) {
        aggregate_kernel<<<AGG_BLOCKS, 256>>>();
        const uint32_t* wh = whi + (size_t)l * 256 * 64;
        const uint32_t* wl = wlo + (size_t)l * 256 * 64;
        const float* bl = b_rel + (size_t)l * DIM;
        if (l == NLAYERS - 1) {
            layer_gemm_kernel<false><<<GEMM_BLOCKS, 256, DSM_BYTES>>>(
                wh, wl, h_ptr, bl, out);
        } else {
            layer_gemm_kernel<true><<<GEMM_BLOCKS, 256, DSM_BYTES>>>(
                wh, wl, h_ptr, bl, h_ptr);
        }
    }
}